// round 6
// baseline (speedup 1.0000x reference)
#include <cuda_runtime.h>
#include <math.h>

#define H 2048
#define H4 512
#define FOURH 8192
#define NT 256   // 8 warps per block, one (layer,j) per warp

// Scratch — h outputs per layer + partial gates (incl. biases) for layers 1,2
__device__ __align__(16) float g_h[3 * H];
__device__ __align__(16) float g_pg[2 * FOURH];

__device__ __forceinline__ float sigmoidf_(float x) { return 1.0f / (1.0f + expf(-x)); }

__device__ __forceinline__ float warp_red(float v) {
    #pragma unroll
    for (int o = 16; o > 0; o >>= 1) v += __shfl_xor_sync(0xffffffffu, v, o);
    return v;
}
__device__ __forceinline__ float d4(float4 a, float4 b) {
    return a.x * b.x + a.y * b.y + a.z * b.z + a.w * b.w;
}

// One warp: 4 dot products (rows j, j+H, j+2H, j+3H of W) against h staged in smem.
// Pure streaming: 64 LDG.128 per thread-warp-row set, zero block syncs.
__device__ __forceinline__ void warp_dot4(const float* __restrict__ W, int j,
                                          const float4* __restrict__ sh,
                                          int lane, float s[4]) {
    #pragma unroll
    for (int g = 0; g < 4; g++) {
        const float4* row = reinterpret_cast<const float4*>(W) + (size_t)(g * H + j) * H4;
        float a0 = 0.f, a1 = 0.f, a2 = 0.f, a3 = 0.f;
        #pragma unroll
        for (int k = 0; k < 16; k += 4) {
            float4 w0 = __ldcs(row + lane + (k + 0) * 32);
            float4 w1 = __ldcs(row + lane + (k + 1) * 32);
            float4 w2 = __ldcs(row + lane + (k + 2) * 32);
            float4 w3 = __ldcs(row + lane + (k + 3) * 32);
            a0 += d4(w0, sh[lane + (k + 0) * 32]);
            a1 += d4(w1, sh[lane + (k + 1) * 32]);
            a2 += d4(w2, sh[lane + (k + 2) * 32]);
            a3 += d4(w3, sh[lane + (k + 3) * 32]);
        }
        s[g] = warp_red((a0 + a1) + (a2 + a3));
    }
}

// Stage 1: 768 blocks. block b: layer = b/256, j-base = (b%256)*8, warp w -> j = jb+w.
// Layer 0 warps do the full LSTM epilogue in lane 0; layers 1,2 write partial gates.
__global__ void __launch_bounds__(NT) k_stage1(
    const float* __restrict__ x,
    const float* __restrict__ hid,
    const float* __restrict__ cell,
    const float* __restrict__ Wih0,
    const float* __restrict__ Whh0,
    const float* __restrict__ bih0, const float* __restrict__ bhh0,
    const float* __restrict__ Whh1,
    const float* __restrict__ bih1, const float* __restrict__ bhh1,
    const float* __restrict__ Whh2,
    const float* __restrict__ bih2, const float* __restrict__ bhh2,
    const float* __restrict__ bout,
    float* __restrict__ out)
{
    __shared__ float4 sh[H4];   // 8 KB: the layer's h vector
    const int b = blockIdx.x;
    const int t = threadIdx.x;
    const int layer = b >> 8;
    const int jb = (b & 255) << 3;

    const float* W = (layer == 0) ? Whh0 : ((layer == 1) ? Whh1 : Whh2);
    const float4* h4 = reinterpret_cast<const float4*>(hid + layer * H);
    sh[t] = h4[t];
    sh[t + NT] = h4[t + NT];
    if (b == 0 && t == 0) out[0] = bout[0];
    __syncthreads();

    const int w = t >> 5, lane = t & 31;
    const int j = jb + w;

    float s[4];
    warp_dot4(W, j, sh, lane, s);

    if (lane == 0) {
        if (layer == 0) {
            const float xv = x[0];
            float gate[4];
            #pragma unroll
            for (int g = 0; g < 4; g++) {
                int r = g * H + j;
                gate[g] = s[g] + xv * Wih0[r] + bih0[r] + bhh0[r];
            }
            float c2 = sigmoidf_(gate[1]) * cell[j] + sigmoidf_(gate[0]) * tanhf(gate[2]);
            float h2 = sigmoidf_(gate[3]) * tanhf(c2);
            g_h[j] = h2;
            out[1 + j] = h2;
            out[1 + 3 * H + j] = c2;
        } else {
            const float* bi = (layer == 1) ? bih1 : bih2;
            const float* bb = (layer == 1) ? bhh1 : bhh2;
            float* pg = g_pg + (layer - 1) * FOURH;
            #pragma unroll
            for (int g = 0; g < 4; g++) {
                int r = g * H + j;
                pg[r] = s[g] + bi[r] + bb[r];
            }
        }
    }
}

// Finish layer (1 or 2): 256 blocks, warp w -> j = b*8+w.
// gates = Wih . h_prev + pg; epilogue; layer 2 adds the output projection.
__global__ void __launch_bounds__(NT) k_finish(
    const float* __restrict__ Wih,
    const float* __restrict__ cell,
    const float* __restrict__ Wout,
    int layer,
    float* __restrict__ out)
{
    __shared__ float4 sh[H4];
    const int b = blockIdx.x;
    const int t = threadIdx.x;
    const int jb = b << 3;

    const float4* h4 = reinterpret_cast<const float4*>(g_h + (layer - 1) * H);
    sh[t] = h4[t];
    sh[t + NT] = h4[t + NT];
    __syncthreads();

    const int w = t >> 5, lane = t & 31;
    const int j = jb + w;

    float s[4];
    warp_dot4(Wih, j, sh, lane, s);

    if (lane == 0) {
        const float* pg = g_pg + (layer - 1) * FOURH;
        float gate[4];
        #pragma unroll
        for (int g = 0; g < 4; g++) gate[g] = s[g] + pg[g * H + j];
        float c2 = sigmoidf_(gate[1]) * cell[layer * H + j] + sigmoidf_(gate[0]) * tanhf(gate[2]);
        float h2 = sigmoidf_(gate[3]) * tanhf(c2);
        g_h[layer * H + j] = h2;
        out[1 + layer * H + j] = h2;
        out[1 + 3 * H + layer * H + j] = c2;
        if (layer == 2) {
            atomicAdd(&out[0], h2 * __ldg(&Wout[j]));
        }
    }
}

extern "C" void kernel_launch(void* const* d_in, const int* in_sizes, int n_in,
                              void* d_out, int out_size) {
    const float* x    = (const float*)d_in[0];
    const float* hid  = (const float*)d_in[1];
    const float* cell = (const float*)d_in[2];
    const float* Wih0 = (const float*)d_in[3];
    const float* Whh0 = (const float*)d_in[4];
    const float* bih0 = (const float*)d_in[5];
    const float* bhh0 = (const float*)d_in[6];
    const float* Wih1 = (const float*)d_in[7];
    const float* Whh1 = (const float*)d_in[8];
    const float* bih1 = (const float*)d_in[9];
    const float* bhh1 = (const float*)d_in[10];
    const float* Wih2 = (const float*)d_in[11];
    const float* Whh2 = (const float*)d_in[12];
    const float* bih2 = (const float*)d_in[13];
    const float* bhh2 = (const float*)d_in[14];
    const float* Wout = (const float*)d_in[15];
    const float* bout = (const float*)d_in[16];
    float* out = (float*)d_out;

    k_stage1<<<3 * 256, NT>>>(x, hid, cell, Wih0,
                              Whh0, bih0, bhh0,
                              Whh1, bih1, bhh1,
                              Whh2, bih2, bhh2, bout, out);
    k_finish<<<256, NT>>>(Wih1, cell, Wout, 1, out);
    k_finish<<<256, NT>>>(Wih2, cell, Wout, 2, out);
}

// round 7
// speedup vs baseline: 1.0334x; 1.0334x over previous
#include <cuda_runtime.h>
#include <math.h>

#define H 2048
#define H4 512
#define FOURH 8192
#define NT 256

// Scratch — h outputs (layers 0,1) + partial gates (incl. biases) for layers 1,2
__device__ __align__(16) float g_h[2 * H];
__device__ __align__(16) float g_pg[2 * FOURH];
__device__ int g_cnt0, g_cntA, g_cntB, g_cnt1, g_done;

__device__ __forceinline__ float sigmoidf_(float x) { return 1.0f / (1.0f + expf(-x)); }

__device__ __forceinline__ float warp_red(float v) {
    #pragma unroll
    for (int o = 16; o > 0; o >>= 1) v += __shfl_xor_sync(0xffffffffu, v, o);
    return v;
}
__device__ __forceinline__ float d4(float4 a, float4 b) {
    return a.x * b.x + a.y * b.y + a.z * b.z + a.w * b.w;
}

// 4 dot products: rows {j, j+H, j+2H, j+3H} of W vs h. All 8 W loads front-batched.
// use_cg: read h via L1-bypassing loads (cross-SM produced data).
__device__ __forceinline__ void dot4(const float* __restrict__ W, int j,
                                     const float* __restrict__ h, bool use_cg,
                                     float s[4]) {
    const int t = threadIdx.x;
    const float4* h4 = reinterpret_cast<const float4*>(h);
    const float4* r0 = reinterpret_cast<const float4*>(W) + (size_t)(0 * H + j) * H4;
    const float4* r1 = reinterpret_cast<const float4*>(W) + (size_t)(1 * H + j) * H4;
    const float4* r2 = reinterpret_cast<const float4*>(W) + (size_t)(2 * H + j) * H4;
    const float4* r3 = reinterpret_cast<const float4*>(W) + (size_t)(3 * H + j) * H4;

    float4 a0 = __ldcs(r0 + t);
    float4 a1 = __ldcs(r1 + t);
    float4 a2 = __ldcs(r2 + t);
    float4 a3 = __ldcs(r3 + t);
    float4 b0 = __ldcs(r0 + t + NT);
    float4 b1 = __ldcs(r1 + t + NT);
    float4 b2 = __ldcs(r2 + t + NT);
    float4 b3 = __ldcs(r3 + t + NT);
    float4 hv0, hv1;
    if (use_cg) { hv0 = __ldcg(h4 + t); hv1 = __ldcg(h4 + t + NT); }
    else        { hv0 = __ldg(h4 + t);  hv1 = __ldg(h4 + t + NT);  }

    s[0] = d4(a0, hv0) + d4(b0, hv1);
    s[1] = d4(a1, hv0) + d4(b1, hv1);
    s[2] = d4(a2, hv0) + d4(b2, hv1);
    s[3] = d4(a3, hv0) + d4(b3, hv1);
}

__device__ __forceinline__ void reduce4(float s[4], float tot[4]) {
    __shared__ float sm[NT / 32][4];
    const int lane = threadIdx.x & 31;
    const int w = threadIdx.x >> 5;
    #pragma unroll
    for (int g = 0; g < 4; g++) s[g] = warp_red(s[g]);
    if (lane == 0) {
        #pragma unroll
        for (int g = 0; g < 4; g++) sm[w][g] = s[g];
    }
    __syncthreads();
    if (threadIdx.x == 0) {
        #pragma unroll
        for (int g = 0; g < 4; g++) {
            float v = 0.0f;
            #pragma unroll
            for (int ww = 0; ww < NT / 32; ww++) v += sm[ww][g];
            tot[g] = v;
        }
    }
}

// Grid (bid order == dependency order; bid-ordered dispatch => spinners only run
// after their producers have retired):
//  grp0 [0,2048):      layer0 full  -> g_h[0..H), cnt0
//  grp1 [2048,4096):   Whh1 partial -> g_pg[0],   cntA
//  grp2 [4096,6144):   Whh2 partial -> g_pg[1],   cntB
//  grp3 [6144,8192):   spin(cnt0,cntA); Wih1 finish -> g_h[H..2H), cnt1
//  grp4 [8192,10240):  spin(cnt1,cntB); Wih2 finish + y projection; reset counters
__global__ void __launch_bounds__(NT, 5) k_fused(
    const float* __restrict__ x,
    const float* __restrict__ hid,
    const float* __restrict__ cell,
    const float* __restrict__ Wih0,
    const float* __restrict__ Whh0,
    const float* __restrict__ bih0, const float* __restrict__ bhh0,
    const float* __restrict__ Wih1,
    const float* __restrict__ Whh1,
    const float* __restrict__ bih1, const float* __restrict__ bhh1,
    const float* __restrict__ Wih2,
    const float* __restrict__ Whh2,
    const float* __restrict__ bih2, const float* __restrict__ bhh2,
    const float* __restrict__ Wout,
    const float* __restrict__ bout,
    float* __restrict__ out)
{
    const int b = blockIdx.x;
    const int t = threadIdx.x;
    const int grp = b >> 11;
    const int j = b & (H - 1);

    if (b == 0 && t == 32) out[0] = bout[0];

    const float* W;
    const float* h;
    bool cg = false;

    if (grp == 0)      { W = Whh0; h = hid; }
    else if (grp == 1) { W = Whh1; h = hid + H; }
    else if (grp == 2) { W = Whh2; h = hid + 2 * H; }
    else {
        W = (grp == 3) ? Wih1 : Wih2;
        h = g_h + (grp - 3) * H;
        cg = true;
        if (t == 0) {
            volatile int* c1 = (grp == 3) ? &g_cnt0 : &g_cnt1;
            volatile int* c2 = (grp == 3) ? &g_cntA : &g_cntB;
            while (*c1 < H || *c2 < H) __nanosleep(64);
        }
        __syncthreads();
        __threadfence();
    }

    float s[4];
    dot4(W, j, h, cg, s);
    float tot[4];
    reduce4(s, tot);

    if (t != 0) return;

    if (grp == 0) {
        const float xv = __ldg(&x[0]);
        float gate[4];
        #pragma unroll
        for (int g = 0; g < 4; g++) {
            int r = g * H + j;
            gate[g] = tot[g] + xv * __ldg(&Wih0[r]) + __ldg(&bih0[r]) + __ldg(&bhh0[r]);
        }
        float c2 = sigmoidf_(gate[1]) * __ldg(&cell[j]) + sigmoidf_(gate[0]) * tanhf(gate[2]);
        float h2 = sigmoidf_(gate[3]) * tanhf(c2);
        g_h[j] = h2;
        out[1 + j] = h2;
        out[1 + 3 * H + j] = c2;
        __threadfence();
        atomicAdd(&g_cnt0, 1);
    } else if (grp <= 2) {
        const float* bi = (grp == 1) ? bih1 : bih2;
        const float* bb = (grp == 1) ? bhh1 : bhh2;
        float* pg = g_pg + (grp - 1) * FOURH;
        #pragma unroll
        for (int g = 0; g < 4; g++) {
            int r = g * H + j;
            pg[r] = tot[g] + __ldg(&bi[r]) + __ldg(&bb[r]);
        }
        __threadfence();
        atomicAdd((grp == 1) ? &g_cntA : &g_cntB, 1);
    } else {
        const int layer = grp - 2;  // 1 or 2
        const float* pg = g_pg + (layer - 1) * FOURH;
        float gate[4];
        #pragma unroll
        for (int g = 0; g < 4; g++) gate[g] = tot[g] + __ldcg(&pg[g * H + j]);
        float c2 = sigmoidf_(gate[1]) * __ldg(&cell[layer * H + j])
                 + sigmoidf_(gate[0]) * tanhf(gate[2]);
        float h2 = sigmoidf_(gate[3]) * tanhf(c2);
        out[1 + layer * H + j] = h2;
        out[1 + 3 * H + layer * H + j] = c2;
        if (layer == 1) {
            g_h[H + j] = h2;
            __threadfence();
            atomicAdd(&g_cnt1, 1);
        } else {
            atomicAdd(&out[0], h2 * __ldg(&Wout[j]));
            int v = atomicAdd(&g_done, 1);
            if (v == H - 1) {  // last block resets sync state for next graph replay
                g_cnt0 = 0; g_cntA = 0; g_cntB = 0; g_cnt1 = 0; g_done = 0;
                __threadfence();
            }
        }
    }
}

extern "C" void kernel_launch(void* const* d_in, const int* in_sizes, int n_in,
                              void* d_out, int out_size) {
    const float* x    = (const float*)d_in[0];
    const float* hid  = (const float*)d_in[1];
    const float* cell = (const float*)d_in[2];
    const float* Wih0 = (const float*)d_in[3];
    const float* Whh0 = (const float*)d_in[4];
    const float* bih0 = (const float*)d_in[5];
    const float* bhh0 = (const float*)d_in[6];
    const float* Wih1 = (const float*)d_in[7];
    const float* Whh1 = (const float*)d_in[8];
    const float* bih1 = (const float*)d_in[9];
    const float* bhh1 = (const float*)d_in[10];
    const float* Wih2 = (const float*)d_in[11];
    const float* Whh2 = (const float*)d_in[12];
    const float* bih2 = (const float*)d_in[13];
    const float* bhh2 = (const float*)d_in[14];
    const float* Wout = (const float*)d_in[15];
    const float* bout = (const float*)d_in[16];
    float* out = (float*)d_out;

    k_fused<<<5 * H, NT>>>(x, hid, cell, Wih0,
                           Whh0, bih0, bhh0,
                           Wih1, Whh1, bih1, bhh1,
                           Wih2, Whh2, bih2, bhh2,
                           Wout, bout, out);
}

// round 8
// speedup vs baseline: 1.0654x; 1.0310x over previous
#include <cuda_runtime.h>
#include <math.h>

#define H 2048
#define H4 512
#define FOURH 8192
#define NT 256   // threads per block; each block handles TWO j values

// Scratch — h outputs per layer + partial gates for layers 1,2
__device__ __align__(16) float g_h[3 * H];
__device__ __align__(16) float g_pg[2 * FOURH];

__device__ __forceinline__ float sigmoidf_(float x) { return 1.0f / (1.0f + expf(-x)); }

__device__ __forceinline__ float warp_red(float v) {
    #pragma unroll
    for (int o = 16; o > 0; o >>= 1) v += __shfl_xor_sync(0xffffffffu, v, o);
    return v;
}
__device__ __forceinline__ float d4(float4 a, float4 b) {
    return a.x * b.x + a.y * b.y + a.z * b.z + a.w * b.w;
}

// 8 dot products: rows {j+g*H} and {j+1+g*H} of W [4H x H] vs h [H].
// h loaded ONCE into registers, reused for both j's. Each batch of 8 W loads
// front-batched into distinct registers before its FMAs.
__device__ __forceinline__ void dot4x2(const float* __restrict__ W, int j,
                                       const float* __restrict__ h, float s[8]) {
    const int t = threadIdx.x;
    const float4* h4 = reinterpret_cast<const float4*>(h);
    float4 hv0 = __ldg(h4 + t);
    float4 hv1 = __ldg(h4 + t + NT);

    #pragma unroll
    for (int jj = 0; jj < 2; jj++) {
        const float4* r0 = reinterpret_cast<const float4*>(W) + (size_t)(0 * H + j + jj) * H4;
        const float4* r1 = reinterpret_cast<const float4*>(W) + (size_t)(1 * H + j + jj) * H4;
        const float4* r2 = reinterpret_cast<const float4*>(W) + (size_t)(2 * H + j + jj) * H4;
        const float4* r3 = reinterpret_cast<const float4*>(W) + (size_t)(3 * H + j + jj) * H4;

        float4 a0 = __ldcs(r0 + t);
        float4 a1 = __ldcs(r1 + t);
        float4 a2 = __ldcs(r2 + t);
        float4 a3 = __ldcs(r3 + t);
        float4 b0 = __ldcs(r0 + t + NT);
        float4 b1 = __ldcs(r1 + t + NT);
        float4 b2 = __ldcs(r2 + t + NT);
        float4 b3 = __ldcs(r3 + t + NT);

        s[jj * 4 + 0] = d4(a0, hv0) + d4(b0, hv1);
        s[jj * 4 + 1] = d4(a1, hv0) + d4(b1, hv1);
        s[jj * 4 + 2] = d4(a2, hv0) + d4(b2, hv1);
        s[jj * 4 + 3] = d4(a3, hv0) + d4(b3, hv1);
    }
}

// Reduce 8 partials with ONE syncthreads; tot valid for threadIdx.x == 0.
__device__ __forceinline__ void reduce8(float s[8], float tot[8]) {
    __shared__ float sm[NT / 32][8];
    const int lane = threadIdx.x & 31;
    const int w = threadIdx.x >> 5;
    #pragma unroll
    for (int g = 0; g < 8; g++) s[g] = warp_red(s[g]);
    if (lane == 0) {
        #pragma unroll
        for (int g = 0; g < 8; g++) sm[w][g] = s[g];
    }
    __syncthreads();
    if (threadIdx.x == 0) {
        #pragma unroll
        for (int g = 0; g < 8; g++) {
            float v = 0.0f;
            #pragma unroll
            for (int ww = 0; ww < NT / 32; ww++) v += sm[ww][g];
            tot[g] = v;
        }
    }
}

// Stage 1: [0,1024) layer0; [1024,2048) Whh1 partial; [2048,3072) Whh2 partial.
// Each block covers j = 2*(b % 1024) and j+1.
__global__ void __launch_bounds__(NT) k_stage1(
    const float* __restrict__ x,
    const float* __restrict__ hid,
    const float* __restrict__ cell,
    const float* __restrict__ Wih0,
    const float* __restrict__ Whh0,
    const float* __restrict__ bih0, const float* __restrict__ bhh0,
    const float* __restrict__ Whh1,
    const float* __restrict__ bih1, const float* __restrict__ bhh1,
    const float* __restrict__ Whh2,
    const float* __restrict__ bih2, const float* __restrict__ bhh2,
    const float* __restrict__ bout,
    float* __restrict__ out)
{
    const int b = blockIdx.x;
    const int layer = b >> 10;
    const int j = (b & 1023) << 1;

    if (b == 0 && threadIdx.x == 32) out[0] = bout[0];

    const float* W = (layer == 0) ? Whh0 : ((layer == 1) ? Whh1 : Whh2);
    const float* h = hid + layer * H;

    float s[8];
    dot4x2(W, j, h, s);
    float tot[8];
    reduce8(s, tot);

    if (threadIdx.x == 0) {
        if (layer == 0) {
            const float xv = x[0];
            #pragma unroll
            for (int jj = 0; jj < 2; jj++) {
                const int jc = j + jj;
                float gate[4];
                #pragma unroll
                for (int g = 0; g < 4; g++) {
                    int r = g * H + jc;
                    gate[g] = tot[jj * 4 + g] + xv * Wih0[r] + bih0[r] + bhh0[r];
                }
                float c2 = sigmoidf_(gate[1]) * cell[jc] + sigmoidf_(gate[0]) * tanhf(gate[2]);
                float h2 = sigmoidf_(gate[3]) * tanhf(c2);
                g_h[jc] = h2;
                out[1 + jc] = h2;
                out[1 + 3 * H + jc] = c2;
            }
        } else {
            const float* bi = (layer == 1) ? bih1 : bih2;
            const float* bb = (layer == 1) ? bhh1 : bhh2;
            float* pg = g_pg + (layer - 1) * FOURH;
            #pragma unroll
            for (int jj = 0; jj < 2; jj++) {
                #pragma unroll
                for (int g = 0; g < 4; g++) {
                    int r = g * H + j + jj;
                    pg[r] = tot[jj * 4 + g] + bi[r] + bb[r];
                }
            }
        }
    }
}

// Finish layer (1 or 2): 1024 blocks, each covers j = 2*b and 2*b+1.
// Layer 2 also accumulates y into out[0] (seeded with bout in stage1).
__global__ void __launch_bounds__(NT) k_finish(
    const float* __restrict__ Wih,
    const float* __restrict__ cell,
    const float* __restrict__ Wout,
    int layer,
    float* __restrict__ out)
{
    const int j = blockIdx.x << 1;
    const float* hin = g_h + (layer - 1) * H;

    float s[8];
    dot4x2(Wih, j, hin, s);
    float tot[8];
    reduce8(s, tot);

    if (threadIdx.x == 0) {
        const float* pg = g_pg + (layer - 1) * FOURH;
        float yacc = 0.0f;
        #pragma unroll
        for (int jj = 0; jj < 2; jj++) {
            const int jc = j + jj;
            float gate[4];
            #pragma unroll
            for (int g = 0; g < 4; g++) gate[g] = tot[jj * 4 + g] + pg[g * H + jc];
            float c2 = sigmoidf_(gate[1]) * cell[layer * H + jc]
                     + sigmoidf_(gate[0]) * tanhf(gate[2]);
            float h2 = sigmoidf_(gate[3]) * tanhf(c2);
            g_h[layer * H + jc] = h2;
            out[1 + layer * H + jc] = h2;
            out[1 + 3 * H + layer * H + jc] = c2;
            if (layer == 2) yacc += h2 * __ldg(&Wout[jc]);
        }
        if (layer == 2) atomicAdd(&out[0], yacc);
    }
}

extern "C" void kernel_launch(void* const* d_in, const int* in_sizes, int n_in,
                              void* d_out, int out_size) {
    const float* x    = (const float*)d_in[0];
    const float* hid  = (const float*)d_in[1];
    const float* cell = (const float*)d_in[2];
    const float* Wih0 = (const float*)d_in[3];
    const float* Whh0 = (const float*)d_in[4];
    const float* bih0 = (const float*)d_in[5];
    const float* bhh0 = (const float*)d_in[6];
    const float* Wih1 = (const float*)d_in[7];
    const float* Whh1 = (const float*)d_in[8];
    const float* bih1 = (const float*)d_in[9];
    const float* bhh1 = (const float*)d_in[10];
    const float* Wih2 = (const float*)d_in[11];
    const float* Whh2 = (const float*)d_in[12];
    const float* bih2 = (const float*)d_in[13];
    const float* bhh2 = (const float*)d_in[14];
    const float* Wout = (const float*)d_in[15];
    const float* bout = (const float*)d_in[16];
    float* out = (float*)d_out;

    k_stage1<<<3 * 1024, NT>>>(x, hid, cell, Wih0,
                               Whh0, bih0, bhh0,
                               Whh1, bih1, bhh1,
                               Whh2, bih2, bhh2, bout, out);
    k_finish<<<1024, NT>>>(Wih1, cell, Wout, 1, out);
    k_finish<<<1024, NT>>>(Wih2, cell, Wout, 2, out);
}